// round 4
// baseline (speedup 1.0000x reference)
#include <cuda_runtime.h>
#include <cuda_bf16.h>
#include <math.h>
#include <stdint.h>

#define Ln 128
#define Bn 4096
#define Dn 300
#define KP2 304                 // K padded to 19 steps of 16
#define NP 320                  // N padded (2 chunks of 160)
#define XROW 656                // 320 bf16 cols + 16B pad
#define WROW 336                // 160 bf16 + 16B pad
#define UROW 328                // 160 bf16 + 8B pad (bank-friendly)
#define SM_X  0
#define SM_W  83968             // 128*656
#define SM_UP 186112            // + 304*336
#define SM_RA 228096            // + 128*328
#define SM_RC 229120
#define DYN_SMEM 230144

// ---------------- device scratch ----------------
__device__ __align__(16) __nv_bfloat16 g_Wbf[KP2 * NP]; // symmetrized, padded bf16 [k][n]
__device__ float g_A0[Ln * Bn], g_A1[Ln * Bn];
__device__ float g_C0[Ln * Bn], g_C1[Ln * Bn];

__device__ __forceinline__ uint32_t smem_to_u32(const void* p) {
    uint32_t a;
    asm("{ .reg .u64 t; cvta.to.shared.u64 t, %1; cvt.u32.u64 %0, t; }" : "=r"(a) : "l"(p));
    return a;
}

#define LDSM_X4(r, addr)                                                        \
    asm volatile("ldmatrix.sync.aligned.m8n8.x4.shared.b16 {%0,%1,%2,%3}, [%4];"\
        : "=r"((r)[0]),"=r"((r)[1]),"=r"((r)[2]),"=r"((r)[3]) : "r"(addr))
#define LDSM_X4T(r, addr)                                                       \
    asm volatile("ldmatrix.sync.aligned.m8n8.x4.trans.shared.b16 {%0,%1,%2,%3}, [%4];"\
        : "=r"((r)[0]),"=r"((r)[1]),"=r"((r)[2]),"=r"((r)[3]) : "r"(addr))
#define MMA16816(d, a, b0, b1)                                                  \
    asm volatile("mma.sync.aligned.m16n8k16.row.col.f32.bf16.bf16.f32 "         \
        "{%0,%1,%2,%3}, {%4,%5,%6,%7}, {%8,%9}, {%0,%1,%2,%3};"                 \
        : "+f"((d)[0]),"+f"((d)[1]),"+f"((d)[2]),"+f"((d)[3])                   \
        : "r"((a)[0]),"r"((a)[1]),"r"((a)[2]),"r"((a)[3]), "r"(b0),"r"(b1))
#define CP_ASYNC16(dst, src)                                                    \
    asm volatile("cp.async.cg.shared.global [%0], [%1], 16;" :: "r"(dst), "l"(src) : "memory")

// ============ kernel 1: bf16 padded symmetric W image [304 k][320 n] ============
__global__ void prepW_kernel(const float* __restrict__ W) {
    int idx = blockIdx.x * 256 + threadIdx.x;
    if (idx >= KP2 * NP) return;
    int k = idx / NP, n = idx % NP;
    float v = 0.0f;
    if (k < Dn && n < Dn) v = W[k * Dn + n] + W[n * Dn + k];
    g_Wbf[idx] = __float2bfloat16(v);
}

// ============ kernel 2: l-sequential HMMA GEMM + all-smem score dots ============
// CTA = (bb, run, ch): b-block of 128, l in [run*8, run*8+8), n-chunk ch (160 cols).
// u_l accumulated by HMMA; a_l = <s_l, u_l>; c_l = <u_{l-1}, s_l> via bf16 uPrev in smem.
__global__ __launch_bounds__(256, 1) void score_kernel(const float* __restrict__ S) {
    extern __shared__ __align__(16) char smem[];
    const uint32_t sb = smem_to_u32(smem);
    const int tid  = threadIdx.x;
    const int lane = tid & 31;
    const int wid  = tid >> 5;
    const int wm   = wid & 3;            // 32-row slice
    const int wn   = wid >> 2;           // 80-col slice within chunk
    const int r0   = 32 * wm;
    const int g    = lane >> 2, q = lane & 3;

    const int bb  = blockIdx.x;          // 0..31
    const int run = blockIdx.y;          // 0..15
    const int ch  = blockIdx.z;          // 0..1
    const int l0  = run * 8;
    float* gA = ch ? g_A1 : g_A0;
    float* gC = ch ? g_C1 : g_C0;

    // ---- load W chunk once (resident for whole run) ----
    for (int idx = tid; idx < KP2 * 20; idx += 256) {
        int k = idx / 20, sg = idx % 20;
        CP_ASYNC16(sb + SM_W + k * WROW + sg * 16,
                   (const char*)g_Wbf + k * (NP * 2) + ch * 320 + sg * 16);
    }
    asm volatile("cp.async.commit_group;" ::: "memory");
    // ---- zero X tail (cols 300..319 + row pad) once ----
    for (int idx = tid; idx < 128 * 7; idx += 256) {
        int r = idx / 7, w = idx % 7;
        *(uint2*)(smem + SM_X + r * XROW + 600 + w * 8) = make_uint2(0u, 0u);
    }
    asm volatile("cp.async.wait_group 0;" ::: "memory");
    __syncthreads();

    const uint32_t aBase0 = sb + SM_X + (r0 + (lane & 15)) * XROW + (lane >> 4) * 16;
    const uint32_t aBase1 = aBase0 + 16 * XROW;
    const uint32_t bBase  = sb + SM_W + (lane & 15) * WROW + (80 * wn + (lane >> 4) * 8) * 2;

    const size_t bbase = (size_t)bb * 128;
    const int lstart = (run == 0) ? 0 : (l0 - 1);

    for (int l = lstart; l < l0 + 8; ++l) {
        __syncthreads();   // X + uPrev + reduce buffers free for reuse
        // ---- stage X tile: 128 rows x 300 fp32 -> bf16 ----
        const float* Sl = S + ((size_t)l * Bn + bbase) * Dn;
        for (int idx = tid; idx < 128 * 75; idx += 256) {
            int r = idx / 75, f = idx % 75;
            float4 v = __ldg((const float4*)(Sl + (size_t)r * Dn) + f);
            __nv_bfloat162 p0 = __floats2bfloat162_rn(v.x, v.y);
            __nv_bfloat162 p1 = __floats2bfloat162_rn(v.z, v.w);
            *(uint2*)(smem + SM_X + r * XROW + f * 8) =
                make_uint2(*(uint32_t*)&p0, *(uint32_t*)&p1);
        }
        __syncthreads();

        // ---- GEMM: 19 k-steps over this 160-col chunk ----
        float acc[2][10][4];
        #pragma unroll
        for (int t = 0; t < 2; t++)
            #pragma unroll
            for (int s = 0; s < 10; s++)
                #pragma unroll
                for (int i = 0; i < 4; i++) acc[t][s][i] = 0.f;

        #pragma unroll 4
        for (int ks = 0; ks < 19; ks++) {
            uint32_t a0[4], a1[4], b[5][4];
            LDSM_X4(a0, aBase0 + ks * 32);
            LDSM_X4(a1, aBase1 + ks * 32);
            const uint32_t bk = bBase + ks * 16 * WROW;
            #pragma unroll
            for (int j = 0; j < 5; j++) LDSM_X4T(b[j], bk + j * 32);
            #pragma unroll
            for (int s = 0; s < 10; s++) {
                const uint32_t b0 = b[s >> 1][(s & 1) * 2];
                const uint32_t b1 = b[s >> 1][(s & 1) * 2 + 1];
                MMA16816(acc[0][s], a0, b0, b1);
                MMA16816(acc[1][s], a1, b0, b1);
            }
        }

        // ---- dots (all smem/register) ----
        if (l >= l0) {
            float aA[2][2] = {{0.f,0.f},{0.f,0.f}};
            float cA[2][2] = {{0.f,0.f},{0.f,0.f}};
            const bool doC = (l > 0);
            #pragma unroll
            for (int t = 0; t < 2; t++) {
                const int rowA = r0 + 16 * t + g;
                const int rowB = rowA + 8;
                #pragma unroll
                for (int s = 0; s < 10; s++) {
                    const int cg   = 80 * wn + 8 * s + 2 * q;        // col in chunk
                    const int colg = ch * 160 + cg;                  // col in X (0..319)
                    uint32_t svA = *(const uint32_t*)(smem + SM_X + rowA * XROW + colg * 2);
                    uint32_t svB = *(const uint32_t*)(smem + SM_X + rowB * XROW + colg * 2);
                    __nv_bfloat162 sA2 = *(__nv_bfloat162*)&svA;
                    __nv_bfloat162 sB2 = *(__nv_bfloat162*)&svB;
                    float sAx = __bfloat162float(sA2.x), sAy = __bfloat162float(sA2.y);
                    float sBx = __bfloat162float(sB2.x), sBy = __bfloat162float(sB2.y);
                    aA[t][0] = fmaf(sAx, acc[t][s][0], fmaf(sAy, acc[t][s][1], aA[t][0]));
                    aA[t][1] = fmaf(sBx, acc[t][s][2], fmaf(sBy, acc[t][s][3], aA[t][1]));
                    if (doC) {
                        uint32_t uA = *(const uint32_t*)(smem + SM_UP + rowA * UROW + cg * 2);
                        uint32_t uB = *(const uint32_t*)(smem + SM_UP + rowB * UROW + cg * 2);
                        __nv_bfloat162 uA2 = *(__nv_bfloat162*)&uA;
                        __nv_bfloat162 uB2 = *(__nv_bfloat162*)&uB;
                        cA[t][0] = fmaf(sAx, __bfloat162float(uA2.x),
                                   fmaf(sAy, __bfloat162float(uA2.y), cA[t][0]));
                        cA[t][1] = fmaf(sBx, __bfloat162float(uB2.x),
                                   fmaf(sBy, __bfloat162float(uB2.y), cA[t][1]));
                    }
                }
            }
            // reduce q lanes, then the 2 n-warps
            float* sRA = (float*)(smem + SM_RA);
            float* sRC = (float*)(smem + SM_RC);
            #pragma unroll
            for (int t = 0; t < 2; t++)
                #pragma unroll
                for (int h = 0; h < 2; h++) {
                    float a = aA[t][h], c = cA[t][h];
                    a += __shfl_xor_sync(0xffffffffu, a, 1);
                    a += __shfl_xor_sync(0xffffffffu, a, 2);
                    c += __shfl_xor_sync(0xffffffffu, c, 1);
                    c += __shfl_xor_sync(0xffffffffu, c, 2);
                    if (q == 0) {
                        int row = r0 + 16 * t + 8 * h + g;
                        sRA[wn * 128 + row] = a;
                        sRC[wn * 128 + row] = c;
                    }
                }
            __syncthreads();
            if (tid < 128) {
                size_t o = (size_t)l * Bn + bbase + tid;
                gA[o] = 0.5f * (sRA[tid] + sRA[128 + tid]);
                if (doC) gC[o] = 0.5f * (sRC[tid] + sRC[128 + tid]);
            }
        }

        // ---- u -> uPrev (bf16 smem); own addresses only, no sync needed ----
        #pragma unroll
        for (int t = 0; t < 2; t++) {
            const int rowA = r0 + 16 * t + g;
            const int rowB = rowA + 8;
            #pragma unroll
            for (int s = 0; s < 10; s++) {
                const int cg = 80 * wn + 8 * s + 2 * q;
                __nv_bfloat162 pA = __floats2bfloat162_rn(acc[t][s][0], acc[t][s][1]);
                __nv_bfloat162 pB = __floats2bfloat162_rn(acc[t][s][2], acc[t][s][3]);
                *(uint32_t*)(smem + SM_UP + rowA * UROW + cg * 2) = *(uint32_t*)&pA;
                *(uint32_t*)(smem + SM_UP + rowB * UROW + cg * 2) = *(uint32_t*)&pB;
            }
        }
    }
}

// ============ kernel 3: mask + softmax + blend (sums chunk partials) ============
__global__ __launch_bounds__(256) void blend_kernel(const float* __restrict__ S,
                                                    const int* __restrict__ sizes,
                                                    float* __restrict__ out) {
    const int l    = blockIdx.y;
    const int warp = threadIdx.x >> 5;
    const int lane = threadIdx.x & 31;
    const int b    = blockIdx.x * 8 + warp;

    const float inv_d = 1.0f / 300.0f;
    const int sz = sizes[b];

    float l1 = (g_A0[l * Bn + b] + g_A1[l * Bn + b]) * inv_d;
    float l0c = (l >= 1 && l < sz)
              ? (g_C0[l * Bn + b] + g_C1[l * Bn + b]) * inv_d : -INFINITY;
    float l2c = (l < Ln - 1 && l < sz - 1)
              ? (g_C0[(l + 1) * Bn + b] + g_C1[(l + 1) * Bn + b]) * inv_d : -INFINITY;

    float mx = fmaxf(l1, fmaxf(l0c, l2c));
    float e0 = expf(l0c - mx), e1 = expf(l1 - mx), e2 = expf(l2c - mx);
    float inv = 1.0f / (e0 + e1 + e2);
    float w0 = e0 * inv, w1 = e1 * inv, w2 = e2 * inv;

    const size_t roff = ((size_t)l * Bn + b) * Dn;
    const size_t slab = (size_t)Bn * Dn;
    const float4* cur = (const float4*)(S + roff);
    float4*       o   = (float4*)(out + roff);
    const bool hasP = (l > 0), hasN = (l < Ln - 1);
    const float4* prv = hasP ? (const float4*)(S + roff - slab) : cur;
    const float4* nxt = hasN ? (const float4*)(S + roff + slab) : cur;

    const float4 z = make_float4(0.f, 0.f, 0.f, 0.f);
    for (int c = lane; c < 75; c += 32) {
        float4 x = cur[c];
        float4 p = hasP ? prv[c] : z;
        float4 n = hasN ? nxt[c] : z;
        float4 r;
        r.x = w1 * x.x + w0 * p.x + w2 * n.x;
        r.y = w1 * x.y + w0 * p.y + w2 * n.y;
        r.z = w1 * x.z + w0 * p.z + w2 * n.z;
        r.w = w1 * x.w + w0 * p.w + w2 * n.w;
        o[c] = r;
    }
}

// ==================== launch ====================
extern "C" void kernel_launch(void* const* d_in, const int* in_sizes, int n_in,
                              void* d_out, int out_size) {
    const float* S     = (const float*)d_in[0];
    const int*   sizes = (const int*)d_in[1];
    const float* W     = (const float*)d_in[2];
    float*       out   = (float*)d_out;
    (void)in_sizes; (void)n_in; (void)out_size;

    prepW_kernel<<<(KP2 * NP + 255) / 256, 256>>>(W);

    cudaFuncSetAttribute(score_kernel, cudaFuncAttributeMaxDynamicSharedMemorySize, DYN_SMEM);
    dim3 g2(32, 16, 2);
    score_kernel<<<g2, 256, DYN_SMEM>>>(S);

    dim3 g3(Bn / 8, Ln);
    blend_kernel<<<g3, 256>>>(S, sizes, out);
}

// round 5
// speedup vs baseline: 1.2069x; 1.2069x over previous
#include <cuda_runtime.h>
#include <cuda_bf16.h>
#include <math.h>
#include <stdint.h>

#define Ln 128
#define Bn 4096
#define Dn 300
#define KP2 304                 // K padded: 19 steps of 16
#define NP 320                  // W gmem row: 320 bf16 (2 chunks of 160)
#define XROW 624                // 304 bf16 + 16B pad
#define WROW 336                // 160 bf16 + 16B pad
#define SM_X  0
#define SM_W  79872             // 128*624
#define SM_RA 182016            // + 304*336
#define SM_RC 183040
#define DYN_SMEM 184064

// ---------------- device scratch ----------------
__device__ __align__(16) __nv_bfloat16 g_Wbf[KP2 * NP]; // symmetrized, padded bf16 [k][n]
__device__ float g_A[Ln * Bn];
__device__ float g_C[Ln * Bn];

__device__ __forceinline__ uint32_t smem_to_u32(const void* p) {
    uint32_t a;
    asm("{ .reg .u64 t; cvta.to.shared.u64 t, %1; cvt.u32.u64 %0, t; }" : "=r"(a) : "l"(p));
    return a;
}

#define LDSM_X4(r, addr)                                                        \
    asm volatile("ldmatrix.sync.aligned.m8n8.x4.shared.b16 {%0,%1,%2,%3}, [%4];"\
        : "=r"((r)[0]),"=r"((r)[1]),"=r"((r)[2]),"=r"((r)[3]) : "r"(addr))
#define LDSM_X4T(r, addr)                                                       \
    asm volatile("ldmatrix.sync.aligned.m8n8.x4.trans.shared.b16 {%0,%1,%2,%3}, [%4];"\
        : "=r"((r)[0]),"=r"((r)[1]),"=r"((r)[2]),"=r"((r)[3]) : "r"(addr))
#define MMA16816(d, a, b0, b1)                                                  \
    asm volatile("mma.sync.aligned.m16n8k16.row.col.f32.bf16.bf16.f32 "         \
        "{%0,%1,%2,%3}, {%4,%5,%6,%7}, {%8,%9}, {%0,%1,%2,%3};"                 \
        : "+f"((d)[0]),"+f"((d)[1]),"+f"((d)[2]),"+f"((d)[3])                   \
        : "r"((a)[0]),"r"((a)[1]),"r"((a)[2]),"r"((a)[3]), "r"(b0),"r"(b1))
#define CP_ASYNC16(dst, src)                                                    \
    asm volatile("cp.async.cg.shared.global [%0], [%1], 16;" :: "r"(dst), "l"(src) : "memory")
#define CP_COMMIT()  asm volatile("cp.async.commit_group;" ::: "memory")
#define CP_WAIT0()   asm volatile("cp.async.wait_group 0;" ::: "memory")

// ============ kernel 1: bf16 padded symmetric W image [304 k][320 n] ============
__global__ void prepW_kernel(const float* __restrict__ W) {
    int idx = blockIdx.x * 256 + threadIdx.x;
    if (idx >= KP2 * NP) return;
    int k = idx / NP, n = idx % NP;
    float v = 0.0f;
    if (k < Dn && n < Dn) v = W[k * Dn + n] + W[n * Dn + k];
    g_Wbf[idx] = __float2bfloat16(v);
}

// ============ kernel 2: HMMA GEMM + fused score dots (pipelined) ============
__global__ __launch_bounds__(256, 1) void score_kernel(const float* __restrict__ S) {
    extern __shared__ __align__(16) char smem[];
    const uint32_t sb = smem_to_u32(smem);
    const int tid  = threadIdx.x;
    const int lane = tid & 31;
    const int wid  = tid >> 5;
    const int wm   = wid & 3;            // 32-row slice
    const int wn   = wid >> 2;           // 80-col slice within chunk
    const int r0   = 32 * wm;
    const int g    = lane >> 2, q = lane & 3;
    const int  tile = blockIdx.x;
    const size_t m0 = (size_t)tile * 128;
    const bool hasPrev = (tile >= 32);

    // ---- 1. issue W chunk-0 fetch (overlaps with X staging below) ----
    for (int idx = tid; idx < KP2 * 20; idx += 256) {
        int k = idx / 20, sg = idx % 20;
        CP_ASYNC16(sb + SM_W + k * WROW + sg * 16,
                   (const char*)g_Wbf + k * (NP * 2) + sg * 16);
    }
    CP_COMMIT();

    // ---- 2. stage X tile: 128 rows x 300 fp32 -> bf16 (cols 300..311 zero) ----
    const float* Sl = S + m0 * Dn;
    for (int idx = tid; idx < 128 * 75; idx += 256) {
        int r = idx / 75, f = idx % 75;
        float4 v = __ldg((const float4*)(Sl + (size_t)r * Dn) + f);
        __nv_bfloat162 p0 = __floats2bfloat162_rn(v.x, v.y);
        __nv_bfloat162 p1 = __floats2bfloat162_rn(v.z, v.w);
        *(uint2*)(smem + SM_X + r * XROW + f * 8) =
            make_uint2(*(uint32_t*)&p0, *(uint32_t*)&p1);
    }
    for (int idx = tid; idx < 128 * 3; idx += 256) {
        int r = idx / 3, w = idx % 3;
        *(uint2*)(smem + SM_X + r * XROW + 600 + w * 8) = make_uint2(0u, 0u);
    }
    CP_WAIT0();
    __syncthreads();

    const uint32_t aBase0 = sb + SM_X + (r0 + (lane & 15)) * XROW + (lane >> 4) * 16;
    const uint32_t aBase1 = aBase0 + 16 * XROW;
    const uint32_t bBase  = sb + SM_W + (lane & 15) * WROW + (80 * wn + (lane >> 4) * 8) * 2;

    float aA[2][2] = {{0.f,0.f},{0.f,0.f}};
    float cA[2][2] = {{0.f,0.f},{0.f,0.f}};

    #pragma unroll
    for (int ch = 0; ch < 2; ch++) {
        // ---- GEMM: 19 k-steps over this 160-col chunk ----
        float acc[2][10][4];
        #pragma unroll
        for (int t = 0; t < 2; t++)
            #pragma unroll
            for (int s = 0; s < 10; s++)
                #pragma unroll
                for (int i = 0; i < 4; i++) acc[t][s][i] = 0.f;

        #pragma unroll 4
        for (int ks = 0; ks < 19; ks++) {
            uint32_t a0[4], a1[4], b[5][4];
            LDSM_X4(a0, aBase0 + ks * 32);
            LDSM_X4(a1, aBase1 + ks * 32);
            const uint32_t bk = bBase + ks * 16 * WROW;
            #pragma unroll
            for (int j = 0; j < 5; j++) LDSM_X4T(b[j], bk + j * 32);
            #pragma unroll
            for (int s = 0; s < 10; s++) {
                const uint32_t b0 = b[s >> 1][(s & 1) * 2];
                const uint32_t b1 = b[s >> 1][(s & 1) * 2 + 1];
                MMA16816(acc[0][s], a0, b0, b1);
                MMA16816(acc[1][s], a1, b0, b1);
            }
        }

        __syncthreads();                 // all warps done reading W smem
        if (ch == 0) {
            // ---- issue W chunk-1 fetch; overlaps with dot epilogue below ----
            for (int idx = tid; idx < KP2 * 20; idx += 256) {
                int k = idx / 20, sg = idx % 20;
                CP_ASYNC16(sb + SM_W + k * WROW + sg * 16,
                           (const char*)g_Wbf + k * (NP * 2) + 320 + sg * 16);
            }
            CP_COMMIT();
        }

        // ---- dot epilogue: self from X smem, prev from gmem (L2-hot) ----
        #pragma unroll
        for (int t = 0; t < 2; t++) {
            const int rowA = r0 + 16 * t + g;
            const int rowB = rowA + 8;
            const float* pA = S + (m0 + rowA - (size_t)Bn) * Dn;
            const float* pB = S + (m0 + rowB - (size_t)Bn) * Dn;
            #pragma unroll
            for (int s = 0; s < 10; s++) {
                const int colg = ch * 160 + 80 * wn + 8 * s + 2 * q;
                if (colg < 304) {        // u == 0 on cols >= 300 (W zero-padded)
                    uint32_t svA = *(const uint32_t*)(smem + SM_X + rowA * XROW + colg * 2);
                    uint32_t svB = *(const uint32_t*)(smem + SM_X + rowB * XROW + colg * 2);
                    __nv_bfloat162 sA2 = *(__nv_bfloat162*)&svA;
                    __nv_bfloat162 sB2 = *(__nv_bfloat162*)&svB;
                    aA[t][0] = fmaf(__bfloat162float(sA2.x), acc[t][s][0],
                               fmaf(__bfloat162float(sA2.y), acc[t][s][1], aA[t][0]));
                    aA[t][1] = fmaf(__bfloat162float(sB2.x), acc[t][s][2],
                               fmaf(__bfloat162float(sB2.y), acc[t][s][3], aA[t][1]));
                    if (hasPrev && colg < Dn) {
                        float2 pvA = __ldg((const float2*)(pA + colg));
                        float2 pvB = __ldg((const float2*)(pB + colg));
                        cA[t][0] = fmaf(pvA.x, acc[t][s][0], fmaf(pvA.y, acc[t][s][1], cA[t][0]));
                        cA[t][1] = fmaf(pvB.x, acc[t][s][2], fmaf(pvB.y, acc[t][s][3], cA[t][1]));
                    }
                }
            }
        }

        if (ch == 0) {
            CP_WAIT0();
            __syncthreads();             // W chunk-1 ready
        }
    }

    // ---- final reduce: q lanes, then the 2 n-warps via smem ----
    float* sRA = (float*)(smem + SM_RA);
    float* sRC = (float*)(smem + SM_RC);
    #pragma unroll
    for (int t = 0; t < 2; t++)
        #pragma unroll
        for (int h = 0; h < 2; h++) {
            float a = aA[t][h], c = cA[t][h];
            a += __shfl_xor_sync(0xffffffffu, a, 1);
            a += __shfl_xor_sync(0xffffffffu, a, 2);
            c += __shfl_xor_sync(0xffffffffu, c, 1);
            c += __shfl_xor_sync(0xffffffffu, c, 2);
            if (q == 0) {
                int row = r0 + 16 * t + 8 * h + g;
                sRA[wn * 128 + row] = a;
                sRC[wn * 128 + row] = c;
            }
        }
    __syncthreads();
    if (tid < 128) {
        g_A[m0 + tid] = 0.5f * (sRA[tid] + sRA[128 + tid]);
        if (hasPrev) g_C[m0 + tid] = 0.5f * (sRC[tid] + sRC[128 + tid]);
    }
}

// ============ kernel 3: mask + softmax + blend ============
__global__ __launch_bounds__(256) void blend_kernel(const float* __restrict__ S,
                                                    const int* __restrict__ sizes,
                                                    float* __restrict__ out) {
    const int l    = blockIdx.y;
    const int warp = threadIdx.x >> 5;
    const int lane = threadIdx.x & 31;
    const int b    = blockIdx.x * 8 + warp;

    const float inv_d = 1.0f / 300.0f;
    const int sz = sizes[b];

    float l1 = g_A[l * Bn + b] * inv_d;
    float l0 = (l >= 1 && l < sz)         ? g_C[l * Bn + b] * inv_d       : -INFINITY;
    float l2 = (l < Ln - 1 && l < sz - 1) ? g_C[(l + 1) * Bn + b] * inv_d : -INFINITY;

    float mx = fmaxf(l1, fmaxf(l0, l2));
    float e0 = expf(l0 - mx), e1 = expf(l1 - mx), e2 = expf(l2 - mx);
    float inv = 1.0f / (e0 + e1 + e2);
    float w0 = e0 * inv, w1 = e1 * inv, w2 = e2 * inv;

    const size_t roff = ((size_t)l * Bn + b) * Dn;
    const size_t slab = (size_t)Bn * Dn;
    const float4* cur = (const float4*)(S + roff);
    float4*       o   = (float4*)(out + roff);
    const bool hasP = (l > 0), hasN = (l < Ln - 1);
    const float4* prv = hasP ? (const float4*)(S + roff - slab) : cur;
    const float4* nxt = hasN ? (const float4*)(S + roff + slab) : cur;

    const float4 z = make_float4(0.f, 0.f, 0.f, 0.f);
    for (int c = lane; c < 75; c += 32) {
        float4 x = cur[c];
        float4 p = hasP ? prv[c] : z;
        float4 n = hasN ? nxt[c] : z;
        float4 r;
        r.x = w1 * x.x + w0 * p.x + w2 * n.x;
        r.y = w1 * x.y + w0 * p.y + w2 * n.y;
        r.z = w1 * x.z + w0 * p.z + w2 * n.z;
        r.w = w1 * x.w + w0 * p.w + w2 * n.w;
        o[c] = r;
    }
}

// ==================== launch ====================
extern "C" void kernel_launch(void* const* d_in, const int* in_sizes, int n_in,
                              void* d_out, int out_size) {
    const float* S     = (const float*)d_in[0];
    const int*   sizes = (const int*)d_in[1];
    const float* W     = (const float*)d_in[2];
    float*       out   = (float*)d_out;
    (void)in_sizes; (void)n_in; (void)out_size;

    prepW_kernel<<<(KP2 * NP + 255) / 256, 256>>>(W);

    cudaFuncSetAttribute(score_kernel, cudaFuncAttributeMaxDynamicSharedMemorySize, DYN_SMEM);
    score_kernel<<<4096, 256, DYN_SMEM>>>(S);

    dim3 g3(Bn / 8, Ln);
    blend_kernel<<<g3, 256>>>(S, sizes, out);
}